// round 1
// baseline (speedup 1.0000x reference)
#include <cuda_runtime.h>
#include <math.h>

#define BB 2
#define HH 480
#define WW 640
#define DD 256
#define HC 60
#define WC 80
#define NN 4800          // HC*WC
#define TOTAL_PIX (BB*HH*WW)

// ---------------- device scratch (no allocs allowed) ----------------
// accumulators: 0 pos1, 1 neg1, 2 npos1, 3 pos2, 4 neg2, 5 npos2, 6 normalization, 7 desc_sum
__device__ double g_acc[8];
__device__ float g_dnorm[BB*NN*DD];    // (b, ij, d) row-major, L2-normalized desc
__device__ float g_wdnorm[BB*NN*DD];
__device__ float g_wy[BB*NN], g_wx[BB*NN];   // warped cell centers (row, col)
__device__ float g_vmc[BB*NN], g_wvmc[BB*NN]; // downsampled masks (0/1)

// ---------------- init ----------------
__global__ void init_kernel() {
    if (threadIdx.x < 8) g_acc[threadIdx.x] = 0.0;
}

// ---------------- detector losses + normalization sum ----------------
__device__ __forceinline__ float warpsum(float v) {
    #pragma unroll
    for (int o = 16; o; o >>= 1) v += __shfl_down_sync(0xffffffffu, v, o);
    return v;
}

__global__ void detector_kernel(const float* __restrict__ prob,
                                const float* __restrict__ ht,
                                const float* __restrict__ vm,
                                const float* __restrict__ wprob,
                                const float* __restrict__ wht,
                                const float* __restrict__ wvm) {
    float vals[7] = {0, 0, 0, 0, 0, 0, 0};
    for (int i = blockIdx.x * blockDim.x + threadIdx.x; i < TOTAL_PIX;
         i += gridDim.x * blockDim.x) {
        {
            float p = prob[i], h = ht[i], v = vm[i];
            float pi = (h == 1.0f) ? 1.f : 0.f;
            float ni = (h < 1.0f) ? 1.f : 0.f;
            float nw = (1.f - h) * (1.f - h); nw *= nw;
            vals[0] += logf(p + 1e-7f) * (1.f - p) * (1.f - p) * pi * v;
            vals[1] += logf(1.f - p + 1e-7f) * p * p * nw * ni * v;
            vals[2] += pi;
        }
        {
            float p = wprob[i], h = wht[i], v = wvm[i];
            float pi = (h == 1.0f) ? 1.f : 0.f;
            float ni = (h < 1.0f) ? 1.f : 0.f;
            float nw = (1.f - h) * (1.f - h); nw *= nw;
            vals[3] += logf(p + 1e-7f) * (1.f - p) * (1.f - p) * pi * v;
            vals[4] += logf(1.f - p + 1e-7f) * p * p * nw * ni * v;
            vals[5] += pi;
        }
        vals[6] += wvm[i];
    }
    __shared__ float w[8];
    int lane = threadIdx.x & 31, warp = threadIdx.x >> 5;
    for (int q = 0; q < 7; q++) {
        float v = warpsum(vals[q]);
        if (lane == 0) w[warp] = v;
        __syncthreads();
        if (threadIdx.x == 0) {
            float s = 0;
            for (int u = 0; u < (int)(blockDim.x >> 5); u++) s += w[u];
            atomicAdd(&g_acc[q], (double)s);
        }
        __syncthreads();
    }
}

// ---------------- descriptor normalize + transpose ----------------
// grid: BB * (NN/32) blocks, 256 threads. tile: 256 d x 32 ij
__global__ void normdesc_kernel(const float* __restrict__ src, float* __restrict__ dst) {
    __shared__ float tile[DD][33];
    __shared__ float part[8][32];
    __shared__ float inv[32];
    int b = blockIdx.x / (NN / 32);
    int jt = blockIdx.x % (NN / 32);
    int base = jt * 32;
    const float* s = src + (size_t)b * DD * NN;
    for (int idx = threadIdx.x; idx < DD * 32; idx += 256) {
        int d = idx >> 5, j = idx & 31;
        tile[d][j] = s[d * NN + base + j];
    }
    __syncthreads();
    {
        int j = threadIdx.x & 31, g = threadIdx.x >> 5;
        float acc = 0;
        for (int d = g; d < DD; d += 8) { float v = tile[d][j]; acc += v * v; }
        part[g][j] = acc;
    }
    __syncthreads();
    if (threadIdx.x < 32) {
        float s2 = 0;
        #pragma unroll
        for (int g2 = 0; g2 < 8; g2++) s2 += part[g2][threadIdx.x];
        inv[threadIdx.x] = 1.0f / fmaxf(sqrtf(s2), 1e-12f);
    }
    __syncthreads();
    float* o = dst + (size_t)b * NN * DD;
    for (int idx = threadIdx.x; idx < 32 * DD; idx += 256) {
        int jj = idx >> 8, d = idx & 255;
        o[(size_t)(base + jj) * DD + d] = tile[d][jj] * inv[jj];
    }
}

// ---------------- warped coords + downsampled masks ----------------
__device__ __forceinline__ float bilinear_ds(const float* __restrict__ img, int i, int j) {
    float sr = (i + 0.5f) * ((float)HH / HC) - 0.5f;
    sr = fminf(fmaxf(sr, 0.f), (float)(HH - 1));
    int r0 = (int)floorf(sr); int r1 = min(r0 + 1, HH - 1); float wr = sr - (float)r0;
    float sc = (j + 0.5f) * ((float)WW / WC) - 0.5f;
    sc = fminf(fmaxf(sc, 0.f), (float)(WW - 1));
    int c0 = (int)floorf(sc); int c1 = min(c0 + 1, WW - 1); float wc = sc - (float)c0;
    float a = img[r0 * WW + c0] * (1.f - wr) + img[r1 * WW + c0] * wr;
    float b = img[r0 * WW + c1] * (1.f - wr) + img[r1 * WW + c1] * wr;
    return a * (1.f - wc) + b * wc;
}

__global__ void coords_kernel(const float* __restrict__ vm,
                              const float* __restrict__ wvm,
                              const float* __restrict__ Hm) {
    int idx = blockIdx.x * blockDim.x + threadIdx.x;
    if (idx >= BB * NN) return;
    int b = idx / NN, ij = idx % NN;
    int i = ij / WC, j = ij % WC;
    float y = (float)(i * 8 + 4), x = (float)(j * 8 + 4);
    const float* Hb = Hm + b * 9;   // Hmat shape (B,1,3,3)
    float w0 = Hb[0] * x + Hb[1] * y + Hb[2];
    float w1 = Hb[3] * x + Hb[4] * y + Hb[5];
    float w2 = Hb[6] * x + Hb[7] * y + Hb[8];
    g_wy[idx] = w1 / w2;   // warped row
    g_wx[idx] = w0 / w2;   // warped col
    g_vmc[idx]  = (bilinear_ds(vm  + (size_t)b * HH * WW, i, j) > 0.5f) ? 1.f : 0.f;
    g_wvmc[idx] = (bilinear_ds(wvm + (size_t)b * HH * WW, i, j) > 0.5f) ? 1.f : 0.f;
}

// ---------------- main: fused GEMM (dot) + loss epilogue ----------------
#define TILE 128
#define KC 16
#define SSTR 132   // padded k-stride (floats); 132%4==0 keeps float4 alignment

__global__ __launch_bounds__(256) void gemm_loss_kernel() {
    __shared__ float As[KC][SSTR];
    __shared__ float Bs[KC][SSTR];
    __shared__ float s_wy[TILE], s_wx[TILE], s_vm[TILE];
    __shared__ float s_cy[TILE], s_cx[TILE], s_wvm[TILE];

    int b = blockIdx.z;
    int i0 = blockIdx.y * TILE;
    int k0 = blockIdx.x * TILE;
    int tid = threadIdx.x;
    const float* A  = g_dnorm  + (size_t)b * NN * DD;
    const float* Bm = g_wdnorm + (size_t)b * NN * DD;

    for (int t = tid; t < TILE; t += 256) {
        int r = i0 + t;
        if (r < NN) { s_wy[t] = g_wy[b*NN + r]; s_wx[t] = g_wx[b*NN + r]; s_vm[t] = g_vmc[b*NN + r]; }
        else        { s_wy[t] = 0.f; s_wx[t] = 0.f; s_vm[t] = 0.f; }
        int c = k0 + t;
        if (c < NN) {
            int kk = c / WC, ll = c % WC;
            s_cy[t] = (float)(kk * 8 + 4); s_cx[t] = (float)(ll * 8 + 4);
            s_wvm[t] = g_wvmc[b*NN + c];
        } else { s_cy[t] = 0.f; s_cx[t] = 0.f; s_wvm[t] = 0.f; }
    }

    float acc[8][8];
    #pragma unroll
    for (int i = 0; i < 8; i++)
        #pragma unroll
        for (int j = 0; j < 8; j++) acc[i][j] = 0.f;

    int kc4 = tid & 3;       // float4 index within K-chunk
    int lr  = tid >> 2;      // 0..63
    int ty  = tid >> 4, tx = tid & 15;
    const float4 z4 = make_float4(0.f, 0.f, 0.f, 0.f);

    for (int kk = 0; kk < DD; kk += KC) {
        int ra = i0 + lr, rb = i0 + lr + 64;
        int ca = k0 + lr, cb = k0 + lr + 64;
        float4 va0 = (ra < NN) ? *(const float4*)(A  + (size_t)ra * DD + kk + kc4 * 4) : z4;
        float4 va1 = (rb < NN) ? *(const float4*)(A  + (size_t)rb * DD + kk + kc4 * 4) : z4;
        float4 vb0 = (ca < NN) ? *(const float4*)(Bm + (size_t)ca * DD + kk + kc4 * 4) : z4;
        float4 vb1 = (cb < NN) ? *(const float4*)(Bm + (size_t)cb * DD + kk + kc4 * 4) : z4;
        __syncthreads();
        As[kc4*4+0][lr] = va0.x; As[kc4*4+1][lr] = va0.y; As[kc4*4+2][lr] = va0.z; As[kc4*4+3][lr] = va0.w;
        As[kc4*4+0][lr+64] = va1.x; As[kc4*4+1][lr+64] = va1.y; As[kc4*4+2][lr+64] = va1.z; As[kc4*4+3][lr+64] = va1.w;
        Bs[kc4*4+0][lr] = vb0.x; Bs[kc4*4+1][lr] = vb0.y; Bs[kc4*4+2][lr] = vb0.z; Bs[kc4*4+3][lr] = vb0.w;
        Bs[kc4*4+0][lr+64] = vb1.x; Bs[kc4*4+1][lr+64] = vb1.y; Bs[kc4*4+2][lr+64] = vb1.z; Bs[kc4*4+3][lr+64] = vb1.w;
        __syncthreads();
        #pragma unroll
        for (int k = 0; k < KC; k++) {
            float a[8], bb[8];
            *(float4*)&a[0]  = *(const float4*)&As[k][ty * 8];
            *(float4*)&a[4]  = *(const float4*)&As[k][ty * 8 + 4];
            *(float4*)&bb[0] = *(const float4*)&Bs[k][tx * 8];
            *(float4*)&bb[4] = *(const float4*)&Bs[k][tx * 8 + 4];
            #pragma unroll
            for (int i = 0; i < 8; i++)
                #pragma unroll
                for (int j = 0; j < 8; j++)
                    acc[i][j] += a[i] * bb[j];
        }
    }

    // fused loss epilogue
    float lsum = 0.f;
    #pragma unroll
    for (int i = 0; i < 8; i++) {
        int rr = ty * 8 + i;
        float wy = s_wy[rr], wx = s_wx[rr], vmr = s_vm[rr];
        #pragma unroll
        for (int j = 0; j < 8; j++) {
            int cc = tx * 8 + j;
            float dot = fmaxf(acc[i][j], 0.f);               // relu
            float pd = fmaxf(1.0f - dot, 0.f);               // POS_MARGIN
            float nd = fmaxf(dot - 0.2f, 0.f);               // NEG_MARGIN
            float dy = s_cy[cc] - wy, dx = s_cx[cc] - wx;
            float s = (sqrtf(dy * dy + dx * dx) <= 7.5f) ? 1.f : 0.f;  // CELL-0.5
            lsum += (250.0f * s * pd + (1.f - s) * nd) * vmr * s_wvm[cc];
        }
    }

    // block reduce -> global double accumulator
    __shared__ float wred[8];
    int lane = tid & 31, warp = tid >> 5;
    float v = warpsum(lsum);
    if (lane == 0) wred[warp] = v;
    __syncthreads();
    if (tid == 0) {
        float s = 0;
        #pragma unroll
        for (int u = 0; u < 8; u++) s += wred[u];
        atomicAdd(&g_acc[7], (double)s);
    }
}

// ---------------- finalize ----------------
__global__ void finalize_kernel(float* __restrict__ out) {
    double np1 = g_acc[2];
    double pl  = (np1 == 0.0) ? -g_acc[1] : -(g_acc[0] + g_acc[1]) / fmax(np1, 1.0);
    double np2 = g_acc[5];
    double wpl = (np2 == 0.0) ? -g_acc[4] : -(g_acc[3] + g_acc[4]) / fmax(np2, 1.0);
    double dl  = g_acc[7] / g_acc[6];
    out[0] = (float)(pl + wpl + 1e-4 * dl);
    out[1] = (float)pl;
    out[2] = (float)wpl;
    out[3] = (float)dl;
}

// ---------------- launch ----------------
extern "C" void kernel_launch(void* const* d_in, const int* in_sizes, int n_in,
                              void* d_out, int out_size) {
    const float* prob  = (const float*)d_in[0];
    const float* ht    = (const float*)d_in[1];
    const float* vm    = (const float*)d_in[2];
    const float* wprob = (const float*)d_in[3];
    const float* wht   = (const float*)d_in[4];
    const float* wvm   = (const float*)d_in[5];
    const float* desc  = (const float*)d_in[6];
    const float* wdesc = (const float*)d_in[7];
    const float* Hm    = (const float*)d_in[8];
    float* out = (float*)d_out;

    init_kernel<<<1, 32>>>();
    detector_kernel<<<1184, 256>>>(prob, ht, vm, wprob, wht, wvm);

    float* dnorm;  cudaGetSymbolAddress((void**)&dnorm,  g_dnorm);
    float* wdnorm; cudaGetSymbolAddress((void**)&wdnorm, g_wdnorm);
    normdesc_kernel<<<BB * (NN / 32), 256>>>(desc,  dnorm);
    normdesc_kernel<<<BB * (NN / 32), 256>>>(wdesc, wdnorm);

    coords_kernel<<<(BB * NN + 255) / 256, 256>>>(vm, wvm, Hm);

    dim3 grid((NN + TILE - 1) / TILE, (NN + TILE - 1) / TILE, BB);
    gemm_loss_kernel<<<grid, 256>>>();

    finalize_kernel<<<1, 1>>>(out);
}

// round 2
// speedup vs baseline: 3.8255x; 3.8255x over previous
#include <cuda_runtime.h>
#include <cuda_bf16.h>
#include <math.h>
#include <stdint.h>

#define BB 2
#define HH 480
#define WW 640
#define DD 256
#define HC 60
#define WC 80
#define NN 4800          // HC*WC
#define TOTAL_PIX (BB*HH*WW)

// ---------------- device scratch ----------------
// acc: 0 pos1, 1 neg1, 2 npos1, 3 pos2, 4 neg2, 5 npos2, 6 normalization, 7 desc_sum
__device__ double g_acc[8];
__device__ __align__(16) __nv_bfloat16 g_dnorm[BB*NN*DD];   // (b, ij, d) bf16 normalized
__device__ __align__(16) __nv_bfloat16 g_wdnorm[BB*NN*DD];
__device__ float4 g_rowgeo[BB*NN];   // {wy, wx, vm_c, 0}
__device__ float4 g_colgeo[BB*NN];   // {cy, cx, wvm_c, 0}

// ---------------- init ----------------
__global__ void init_kernel() {
    if (threadIdx.x < 8) g_acc[threadIdx.x] = 0.0;
}

__device__ __forceinline__ float warpsum(float v) {
    #pragma unroll
    for (int o = 16; o; o >>= 1) v += __shfl_down_sync(0xffffffffu, v, o);
    return v;
}

__device__ __forceinline__ uint32_t smem_u32(const void* p) {
    uint32_t a;
    asm("{ .reg .u64 t; cvta.to.shared.u64 t, %1; cvt.u32.u64 %0, t; }" : "=r"(a) : "l"(p));
    return a;
}

// ---------------- detector losses + normalization sum ----------------
__global__ void detector_kernel(const float* __restrict__ prob,
                                const float* __restrict__ ht,
                                const float* __restrict__ vm,
                                const float* __restrict__ wprob,
                                const float* __restrict__ wht,
                                const float* __restrict__ wvm) {
    float vals[7] = {0, 0, 0, 0, 0, 0, 0};
    for (int i = blockIdx.x * blockDim.x + threadIdx.x; i < TOTAL_PIX;
         i += gridDim.x * blockDim.x) {
        {
            float p = prob[i], h = ht[i], v = vm[i];
            float pi = (h == 1.0f) ? 1.f : 0.f;
            float ni = (h < 1.0f) ? 1.f : 0.f;
            float nw = (1.f - h) * (1.f - h); nw *= nw;
            vals[0] += logf(p + 1e-7f) * (1.f - p) * (1.f - p) * pi * v;
            vals[1] += logf(1.f - p + 1e-7f) * p * p * nw * ni * v;
            vals[2] += pi;
        }
        {
            float p = wprob[i], h = wht[i], v = wvm[i];
            float pi = (h == 1.0f) ? 1.f : 0.f;
            float ni = (h < 1.0f) ? 1.f : 0.f;
            float nw = (1.f - h) * (1.f - h); nw *= nw;
            vals[3] += logf(p + 1e-7f) * (1.f - p) * (1.f - p) * pi * v;
            vals[4] += logf(1.f - p + 1e-7f) * p * p * nw * ni * v;
            vals[5] += pi;
        }
        vals[6] += wvm[i];
    }
    __shared__ float w[8];
    int lane = threadIdx.x & 31, warp = threadIdx.x >> 5;
    for (int q = 0; q < 7; q++) {
        float v = warpsum(vals[q]);
        if (lane == 0) w[warp] = v;
        __syncthreads();
        if (threadIdx.x == 0) {
            float s = 0;
            for (int u = 0; u < (int)(blockDim.x >> 5); u++) s += w[u];
            atomicAdd(&g_acc[q], (double)s);
        }
        __syncthreads();
    }
}

// ---------------- descriptor normalize + transpose (fp32 -> bf16) ----------------
__global__ void normdesc_kernel(const float* __restrict__ src, __nv_bfloat16* __restrict__ dst) {
    __shared__ float tile[DD][33];
    __shared__ float part[8][32];
    __shared__ float inv[32];
    int b = blockIdx.x / (NN / 32);
    int jt = blockIdx.x % (NN / 32);
    int base = jt * 32;
    const float* s = src + (size_t)b * DD * NN;
    for (int idx = threadIdx.x; idx < DD * 32; idx += 256) {
        int d = idx >> 5, j = idx & 31;
        tile[d][j] = s[d * NN + base + j];
    }
    __syncthreads();
    {
        int j = threadIdx.x & 31, g = threadIdx.x >> 5;
        float acc = 0;
        for (int d = g; d < DD; d += 8) { float v = tile[d][j]; acc += v * v; }
        part[g][j] = acc;
    }
    __syncthreads();
    if (threadIdx.x < 32) {
        float s2 = 0;
        #pragma unroll
        for (int g2 = 0; g2 < 8; g2++) s2 += part[g2][threadIdx.x];
        inv[threadIdx.x] = 1.0f / fmaxf(sqrtf(s2), 1e-12f);
    }
    __syncthreads();
    __nv_bfloat16* o = dst + (size_t)b * NN * DD;
    for (int idx = threadIdx.x; idx < 32 * DD; idx += 256) {
        int jj = idx >> 8, d = idx & 255;
        o[(size_t)(base + jj) * DD + d] = __float2bfloat16(tile[d][jj] * inv[jj]);
    }
}

// ---------------- warped coords + downsampled masks -> geometry float4s ----------------
__device__ __forceinline__ float bilinear_ds(const float* __restrict__ img, int i, int j) {
    float sr = (i + 0.5f) * ((float)HH / HC) - 0.5f;
    sr = fminf(fmaxf(sr, 0.f), (float)(HH - 1));
    int r0 = (int)floorf(sr); int r1 = min(r0 + 1, HH - 1); float wr = sr - (float)r0;
    float sc = (j + 0.5f) * ((float)WW / WC) - 0.5f;
    sc = fminf(fmaxf(sc, 0.f), (float)(WW - 1));
    int c0 = (int)floorf(sc); int c1 = min(c0 + 1, WW - 1); float wc = sc - (float)c0;
    float a = img[r0 * WW + c0] * (1.f - wr) + img[r1 * WW + c0] * wr;
    float b = img[r0 * WW + c1] * (1.f - wr) + img[r1 * WW + c1] * wr;
    return a * (1.f - wc) + b * wc;
}

__global__ void coords_kernel(const float* __restrict__ vm,
                              const float* __restrict__ wvm,
                              const float* __restrict__ Hm) {
    int idx = blockIdx.x * blockDim.x + threadIdx.x;
    if (idx >= BB * NN) return;
    int b = idx / NN, ij = idx % NN;
    int i = ij / WC, j = ij % WC;
    float y = (float)(i * 8 + 4), x = (float)(j * 8 + 4);
    const float* Hb = Hm + b * 9;
    float w0 = Hb[0] * x + Hb[1] * y + Hb[2];
    float w1 = Hb[3] * x + Hb[4] * y + Hb[5];
    float w2 = Hb[6] * x + Hb[7] * y + Hb[8];
    float vmc  = (bilinear_ds(vm  + (size_t)b * HH * WW, i, j) > 0.5f) ? 1.f : 0.f;
    float wvmc = (bilinear_ds(wvm + (size_t)b * HH * WW, i, j) > 0.5f) ? 1.f : 0.f;
    g_rowgeo[idx] = make_float4(w1 / w2, w0 / w2, vmc, 0.f);
    g_colgeo[idx] = make_float4(y, x, wvmc, 0.f);
}

// ---------------- main: bf16 tensor-core GEMM + fused loss epilogue ----------------
#define TILE 128
#define KC 32
#define ASTR 40   // smem row stride in halfs: 80B, 16B-aligned, 5r%8 permutation -> conflict-free ldmatrix

__device__ __forceinline__ float lossterm(float acc, float4 r, float4 c) {
    float dot = fmaxf(acc, 0.f);
    float pd = fmaxf(1.0f - dot, 0.f);
    float nd = fmaxf(dot - 0.2f, 0.f);
    float dy = c.x - r.x, dx = c.y - r.y;
    float d2 = dy * dy + dx * dx;
    float w = r.z * c.z;
    return (d2 <= 56.25f) ? 250.f * pd * w : nd * w;   // (CELL-0.5)^2 = 56.25
}

__global__ __launch_bounds__(256) void gemm_loss_kernel() {
    __shared__ __align__(16) __nv_bfloat16 As[TILE * ASTR];
    __shared__ __align__(16) __nv_bfloat16 Bs[TILE * ASTR];
    __shared__ float4 s_row[TILE], s_col[TILE];

    int b = blockIdx.z;
    int i0 = blockIdx.y * TILE;
    int j0 = blockIdx.x * TILE;
    int tid = threadIdx.x;

    if (tid < TILE) {
        int r = i0 + tid;
        s_row[tid] = (r < NN) ? g_rowgeo[b * NN + r] : make_float4(0.f, 0.f, 0.f, 0.f);
    } else {
        int t = tid - TILE;
        int c = j0 + t;
        s_col[t] = (c < NN) ? g_colgeo[b * NN + c] : make_float4(0.f, 0.f, 0.f, 0.f);
    }

    const __nv_bfloat16* A  = g_dnorm  + (size_t)b * NN * DD;
    const __nv_bfloat16* Bm = g_wdnorm + (size_t)b * NN * DD;

    int lrow = tid >> 1, lhalf = tid & 1;
    int ra = i0 + lrow, ca = j0 + lrow;
    bool okA = ra < NN, okB = ca < NN;
    const uint4* Ag = (const uint4*)(A  + (size_t)(okA ? ra : 0) * DD + lhalf * 16);
    const uint4* Bg = (const uint4*)(Bm + (size_t)(okB ? ca : 0) * DD + lhalf * 16);
    const uint4 z4 = make_uint4(0, 0, 0, 0);

    uint4 pa0 = okA ? Ag[0] : z4;
    uint4 pa1 = okA ? Ag[1] : z4;
    uint4 pb0 = okB ? Bg[0] : z4;
    uint4 pb1 = okB ? Bg[1] : z4;

    int wid = tid >> 5, lane = tid & 31;
    int m_base = (wid >> 2) * 64;     // 0 or 64
    int n_base = (wid & 3) * 32;      // 0,32,64,96
    int g = lane >> 3, lr = lane & 7;

    float c[4][4][4];
    #pragma unroll
    for (int mt = 0; mt < 4; mt++)
        #pragma unroll
        for (int nt = 0; nt < 4; nt++)
            #pragma unroll
            for (int q = 0; q < 4; q++) c[mt][nt][q] = 0.f;

    uint32_t As_base = smem_u32(As), Bs_base = smem_u32(Bs);
    // per-lane ldmatrix addresses (bytes), constant except k-offset
    // A x4: row = m_base + mt*16 + (g&1)*8 + lr ; koff = (g>>1)*8 + ks
    // B x2: row = n_base + nt*8 + lr ; koff = (g&1)*8 + ks
    uint32_t a_row_off = (uint32_t)((m_base + (g & 1) * 8 + lr) * ASTR + (g >> 1) * 8) * 2;
    uint32_t b_row_off = (uint32_t)((n_base + lr) * ASTR + (g & 1) * 8) * 2;

    for (int kk = 0; kk < DD; kk += KC) {
        __syncthreads();
        {
            uint4* Asw = (uint4*)(As + lrow * ASTR + lhalf * 16);
            Asw[0] = pa0; Asw[1] = pa1;
            uint4* Bsw = (uint4*)(Bs + lrow * ASTR + lhalf * 16);
            Bsw[0] = pb0; Bsw[1] = pb1;
        }
        __syncthreads();
        if (kk + KC < DD) {
            int o = (kk + KC) >> 3;
            pa0 = okA ? Ag[o]     : z4;
            pa1 = okA ? Ag[o + 1] : z4;
            pb0 = okB ? Bg[o]     : z4;
            pb1 = okB ? Bg[o + 1] : z4;
        }
        #pragma unroll
        for (int ks = 0; ks < KC; ks += 16) {
            uint32_t af[4][4], bf[4][2];
            #pragma unroll
            for (int mt = 0; mt < 4; mt++) {
                uint32_t addr = As_base + a_row_off + (uint32_t)(mt * 16 * ASTR + ks) * 2;
                asm volatile("ldmatrix.sync.aligned.m8n8.x4.shared.b16 {%0,%1,%2,%3}, [%4];"
                             : "=r"(af[mt][0]), "=r"(af[mt][1]), "=r"(af[mt][2]), "=r"(af[mt][3])
                             : "r"(addr));
            }
            #pragma unroll
            for (int nt = 0; nt < 4; nt++) {
                uint32_t addr = Bs_base + b_row_off + (uint32_t)(nt * 8 * ASTR + ks) * 2;
                asm volatile("ldmatrix.sync.aligned.m8n8.x2.shared.b16 {%0,%1}, [%2];"
                             : "=r"(bf[nt][0]), "=r"(bf[nt][1])
                             : "r"(addr));
            }
            #pragma unroll
            for (int mt = 0; mt < 4; mt++)
                #pragma unroll
                for (int nt = 0; nt < 4; nt++) {
                    asm volatile(
                        "mma.sync.aligned.m16n8k16.row.col.f32.bf16.bf16.f32 "
                        "{%0,%1,%2,%3}, {%4,%5,%6,%7}, {%8,%9}, {%0,%1,%2,%3};"
                        : "+f"(c[mt][nt][0]), "+f"(c[mt][nt][1]),
                          "+f"(c[mt][nt][2]), "+f"(c[mt][nt][3])
                        : "r"(af[mt][0]), "r"(af[mt][1]), "r"(af[mt][2]), "r"(af[mt][3]),
                          "r"(bf[nt][0]), "r"(bf[nt][1]));
                }
        }
    }

    // fused epilogue: C-fragment layout: lane holds (m = qr, qr+8; n = qc, qc+1)
    int qr = lane >> 2, qc = (lane & 3) * 2;
    float lsum = 0.f;
    #pragma unroll
    for (int mt = 0; mt < 4; mt++) {
        float4 r0 = s_row[m_base + mt * 16 + qr];
        float4 r1 = s_row[m_base + mt * 16 + qr + 8];
        #pragma unroll
        for (int nt = 0; nt < 4; nt++) {
            float4 c0 = s_col[n_base + nt * 8 + qc];
            float4 c1 = s_col[n_base + nt * 8 + qc + 1];
            lsum += lossterm(c[mt][nt][0], r0, c0);
            lsum += lossterm(c[mt][nt][1], r0, c1);
            lsum += lossterm(c[mt][nt][2], r1, c0);
            lsum += lossterm(c[mt][nt][3], r1, c1);
        }
    }

    __shared__ float wred[8];
    float v = warpsum(lsum);
    if (lane == 0) wred[wid] = v;
    __syncthreads();
    if (tid == 0) {
        float s = 0;
        #pragma unroll
        for (int u = 0; u < 8; u++) s += wred[u];
        atomicAdd(&g_acc[7], (double)s);
    }
}

// ---------------- finalize ----------------
__global__ void finalize_kernel(float* __restrict__ out) {
    double np1 = g_acc[2];
    double pl  = (np1 == 0.0) ? -g_acc[1] : -(g_acc[0] + g_acc[1]) / fmax(np1, 1.0);
    double np2 = g_acc[5];
    double wpl = (np2 == 0.0) ? -g_acc[4] : -(g_acc[3] + g_acc[4]) / fmax(np2, 1.0);
    double dl  = g_acc[7] / g_acc[6];
    out[0] = (float)(pl + wpl + 1e-4 * dl);
    out[1] = (float)pl;
    out[2] = (float)wpl;
    out[3] = (float)dl;
}

// ---------------- launch ----------------
extern "C" void kernel_launch(void* const* d_in, const int* in_sizes, int n_in,
                              void* d_out, int out_size) {
    const float* prob  = (const float*)d_in[0];
    const float* ht    = (const float*)d_in[1];
    const float* vm    = (const float*)d_in[2];
    const float* wprob = (const float*)d_in[3];
    const float* wht   = (const float*)d_in[4];
    const float* wvm   = (const float*)d_in[5];
    const float* desc  = (const float*)d_in[6];
    const float* wdesc = (const float*)d_in[7];
    const float* Hm    = (const float*)d_in[8];
    float* out = (float*)d_out;

    init_kernel<<<1, 32>>>();
    detector_kernel<<<1184, 256>>>(prob, ht, vm, wprob, wht, wvm);

    __nv_bfloat16* dnorm;  cudaGetSymbolAddress((void**)&dnorm,  g_dnorm);
    __nv_bfloat16* wdnorm; cudaGetSymbolAddress((void**)&wdnorm, g_wdnorm);
    normdesc_kernel<<<BB * (NN / 32), 256>>>(desc,  dnorm);
    normdesc_kernel<<<BB * (NN / 32), 256>>>(wdesc, wdnorm);

    coords_kernel<<<(BB * NN + 255) / 256, 256>>>(vm, wvm, Hm);

    dim3 grid((NN + TILE - 1) / TILE, (NN + TILE - 1) / TILE, BB);
    gemm_loss_kernel<<<grid, 256>>>();

    finalize_kernel<<<1, 1>>>(out);
}

// round 5
// speedup vs baseline: 4.4818x; 1.1716x over previous
#include <cuda_runtime.h>
#include <cuda_bf16.h>
#include <math.h>
#include <stdint.h>

#define BB 2
#define HH 480
#define WW 640
#define DD 256
#define HC 60
#define WC 80
#define NN 4800          // HC*WC
#define TOTAL_PIX (BB*HH*WW)

// ---------------- device scratch ----------------
// acc: 0 pos1, 1 neg1, 2 npos1, 3 pos2, 4 neg2, 5 npos2, 6 normalization, 7 desc_sum
__device__ double g_acc[8];
__device__ __align__(16) __nv_bfloat16 g_dnorm[BB*NN*DD];   // (b, ij, d) bf16 normalized
__device__ __align__(16) __nv_bfloat16 g_wdnorm[BB*NN*DD];
__device__ float4 g_rowgeo[BB*NN];   // {wy, wx, vm_c, 0}
__device__ float4 g_colgeo[BB*NN];   // {cy, cx, wvm_c, 0}

// ---------------- helpers ----------------
__device__ __forceinline__ float warpsum(float v) {
    #pragma unroll
    for (int o = 16; o; o >>= 1) v += __shfl_down_sync(0xffffffffu, v, o);
    return v;
}

__device__ __forceinline__ uint32_t smem_u32(const void* p) {
    uint32_t a;
    asm("{ .reg .u64 t; cvta.to.shared.u64 t, %1; cvt.u32.u64 %0, t; }" : "=r"(a) : "l"(p));
    return a;
}

__device__ __forceinline__ void cp_async16(uint32_t dst, const void* src, uint32_t bytes) {
    asm volatile("cp.async.cg.shared.global [%0], [%1], 16, %2;"
                 :: "r"(dst), "l"(src), "r"(bytes) : "memory");
}
#define CP_COMMIT() asm volatile("cp.async.commit_group;" ::: "memory")
#define CP_WAIT(n)  asm volatile("cp.async.wait_group %0;" :: "n"(n) : "memory")

// ---------------- init ----------------
__global__ void init_kernel() {
    if (threadIdx.x < 8) g_acc[threadIdx.x] = 0.0;
}

// ---------------- detector losses + normalization sum ----------------
__global__ void detector_kernel(const float* __restrict__ prob,
                                const float* __restrict__ ht,
                                const float* __restrict__ vm,
                                const float* __restrict__ wprob,
                                const float* __restrict__ wht,
                                const float* __restrict__ wvm) {
    float vals[7] = {0, 0, 0, 0, 0, 0, 0};
    for (int i = blockIdx.x * blockDim.x + threadIdx.x; i < TOTAL_PIX;
         i += gridDim.x * blockDim.x) {
        {
            float p = prob[i], h = ht[i], v = vm[i];
            float pi = (h == 1.0f) ? 1.f : 0.f;
            float ni = (h < 1.0f) ? 1.f : 0.f;
            float nw = (1.f - h) * (1.f - h); nw *= nw;
            vals[0] += logf(p + 1e-7f) * (1.f - p) * (1.f - p) * pi * v;
            vals[1] += logf(1.f - p + 1e-7f) * p * p * nw * ni * v;
            vals[2] += pi;
        }
        {
            float p = wprob[i], h = wht[i], v = wvm[i];
            float pi = (h == 1.0f) ? 1.f : 0.f;
            float ni = (h < 1.0f) ? 1.f : 0.f;
            float nw = (1.f - h) * (1.f - h); nw *= nw;
            vals[3] += logf(p + 1e-7f) * (1.f - p) * (1.f - p) * pi * v;
            vals[4] += logf(1.f - p + 1e-7f) * p * p * nw * ni * v;
            vals[5] += pi;
        }
        vals[6] += wvm[i];
    }
    __shared__ float w[8];
    int lane = threadIdx.x & 31, warp = threadIdx.x >> 5;
    for (int q = 0; q < 7; q++) {
        float v = warpsum(vals[q]);
        if (lane == 0) w[warp] = v;
        __syncthreads();
        if (threadIdx.x == 0) {
            float s = 0;
            for (int u = 0; u < (int)(blockDim.x >> 5); u++) s += w[u];
            atomicAdd(&g_acc[q], (double)s);
        }
        __syncthreads();
    }
}

// ---------------- descriptor normalize + transpose (fp32 -> bf16), both tensors ----------------
__global__ void normdesc_kernel(const float* __restrict__ src0, __nv_bfloat16* __restrict__ dst0,
                                const float* __restrict__ src1, __nv_bfloat16* __restrict__ dst1) {
    __shared__ float tile[DD][33];
    __shared__ float part[8][32];
    __shared__ float inv[32];
    int which = blockIdx.x >= BB * (NN / 32);
    int blk = blockIdx.x - which * BB * (NN / 32);
    const float* src = which ? src1 : src0;
    __nv_bfloat16* dst = which ? dst1 : dst0;
    int b = blk / (NN / 32);
    int jt = blk % (NN / 32);
    int base = jt * 32;
    const float* s = src + (size_t)b * DD * NN;
    for (int idx = threadIdx.x; idx < DD * 32; idx += 256) {
        int d = idx >> 5, j = idx & 31;
        tile[d][j] = s[d * NN + base + j];
    }
    __syncthreads();
    {
        int j = threadIdx.x & 31, g = threadIdx.x >> 5;
        float acc = 0;
        for (int d = g; d < DD; d += 8) { float v = tile[d][j]; acc += v * v; }
        part[g][j] = acc;
    }
    __syncthreads();
    if (threadIdx.x < 32) {
        float s2 = 0;
        #pragma unroll
        for (int g2 = 0; g2 < 8; g2++) s2 += part[g2][threadIdx.x];
        inv[threadIdx.x] = 1.0f / fmaxf(sqrtf(s2), 1e-12f);
    }
    __syncthreads();
    __nv_bfloat16* o = dst + (size_t)b * NN * DD;
    for (int idx = threadIdx.x; idx < 32 * DD; idx += 256) {
        int jj = idx >> 8, d = idx & 255;
        o[(size_t)(base + jj) * DD + d] = __float2bfloat16(tile[d][jj] * inv[jj]);
    }
}

// ---------------- warped coords + downsampled masks ----------------
__device__ __forceinline__ float bilinear_ds(const float* __restrict__ img, int i, int j) {
    float sr = (i + 0.5f) * ((float)HH / HC) - 0.5f;
    sr = fminf(fmaxf(sr, 0.f), (float)(HH - 1));
    int r0 = (int)floorf(sr); int r1 = min(r0 + 1, HH - 1); float wr = sr - (float)r0;
    float sc = (j + 0.5f) * ((float)WW / WC) - 0.5f;
    sc = fminf(fmaxf(sc, 0.f), (float)(WW - 1));
    int c0 = (int)floorf(sc); int c1 = min(c0 + 1, WW - 1); float wc = sc - (float)c0;
    float a = img[r0 * WW + c0] * (1.f - wr) + img[r1 * WW + c0] * wr;
    float b = img[r0 * WW + c1] * (1.f - wr) + img[r1 * WW + c1] * wr;
    return a * (1.f - wc) + b * wc;
}

__global__ void coords_kernel(const float* __restrict__ vm,
                              const float* __restrict__ wvm,
                              const float* __restrict__ Hm) {
    int idx = blockIdx.x * blockDim.x + threadIdx.x;
    if (idx >= BB * NN) return;
    int b = idx / NN, ij = idx % NN;
    int i = ij / WC, j = ij % WC;
    float y = (float)(i * 8 + 4), x = (float)(j * 8 + 4);
    const float* Hb = Hm + b * 9;
    float w0 = Hb[0] * x + Hb[1] * y + Hb[2];
    float w1 = Hb[3] * x + Hb[4] * y + Hb[5];
    float w2 = Hb[6] * x + Hb[7] * y + Hb[8];
    float vmc  = (bilinear_ds(vm  + (size_t)b * HH * WW, i, j) > 0.5f) ? 1.f : 0.f;
    float wvmc = (bilinear_ds(wvm + (size_t)b * HH * WW, i, j) > 0.5f) ? 1.f : 0.f;
    g_rowgeo[idx] = make_float4(w1 / w2, w0 / w2, vmc, 0.f);
    g_colgeo[idx] = make_float4(y, x, wvmc, 0.f);
}

// ---------------- main: bf16 mma.sync GEMM, cp.async double-buffered ----------------
#define TILE 128
#define KC 32
#define ASTR 40   // padded k-stride (halfs): 80B rows, 16B aligned, conflict-free ldmatrix
#define ABYTES (TILE * ASTR * 2)
#define NCHUNK (DD / KC)

__device__ __forceinline__ float lossterm(float acc, float4 r, float4 c) {
    float dot = fmaxf(acc, 0.f);
    float pd = fmaxf(1.0f - dot, 0.f);
    float nd = fmaxf(dot - 0.2f, 0.f);
    float dy = c.x - r.x, dx = c.y - r.y;
    float d2 = dy * dy + dx * dx;
    float w = r.z * c.z;
    return (d2 <= 56.25f) ? 250.f * pd * w : nd * w;   // (CELL-0.5)^2 = 56.25
}

__global__ __launch_bounds__(256, 2) void gemm_loss_kernel() {
    __shared__ __align__(16) __nv_bfloat16 As[2][TILE * ASTR];
    __shared__ __align__(16) __nv_bfloat16 Bs[2][TILE * ASTR];
    __shared__ float4 s_row[TILE], s_col[TILE];
    __shared__ float wred[8];

    int b = blockIdx.z;
    int i0 = blockIdx.y * TILE;
    int j0 = blockIdx.x * TILE;
    int tid = threadIdx.x;
    int wid = tid >> 5, lane = tid & 31;

    if (tid < TILE) {
        int r = i0 + tid;
        s_row[tid] = (r < NN) ? g_rowgeo[b * NN + r] : make_float4(0.f, 0.f, 0.f, 0.f);
    } else {
        int t = tid - TILE;
        int c = j0 + t;
        s_col[t] = (c < NN) ? g_colgeo[b * NN + c] : make_float4(0.f, 0.f, 0.f, 0.f);
    }

    const char* A  = (const char*)(g_dnorm  + (size_t)b * NN * DD);
    const char* Bm = (const char*)(g_wdnorm + (size_t)b * NN * DD);

    // cp.async geometry: each KC-chunk row = 64B = 4x16B; 128 rows * 4 = 512 segs
    // per matrix; 256 threads -> 2 segs each.
    int idxA0 = tid * 2, idxA1 = tid * 2 + 1;
    int rowA0 = idxA0 >> 2, cA0 = idxA0 & 3;
    int rowA1 = idxA1 >> 2, cA1 = idxA1 & 3;
    uint32_t okA0 = (i0 + rowA0 < NN) ? 16u : 0u;
    uint32_t okA1 = (i0 + rowA1 < NN) ? 16u : 0u;
    uint32_t okB0 = (j0 + rowA0 < NN) ? 16u : 0u;
    uint32_t okB1 = (j0 + rowA1 < NN) ? 16u : 0u;
    const char* gA0 = A  + (size_t)(i0 + rowA0) * (DD * 2) + cA0 * 16;
    const char* gA1 = A  + (size_t)(i0 + rowA1) * (DD * 2) + cA1 * 16;
    const char* gB0 = Bm + (size_t)(j0 + rowA0) * (DD * 2) + cA0 * 16;
    const char* gB1 = Bm + (size_t)(j0 + rowA1) * (DD * 2) + cA1 * 16;
    uint32_t sA0 = smem_u32(As) + rowA0 * (ASTR * 2) + cA0 * 16;
    uint32_t sA1 = smem_u32(As) + rowA1 * (ASTR * 2) + cA1 * 16;
    uint32_t sB0 = smem_u32(Bs) + rowA0 * (ASTR * 2) + cA0 * 16;
    uint32_t sB1 = smem_u32(Bs) + rowA1 * (ASTR * 2) + cA1 * 16;

    int m_base = (wid >> 2) * 64;     // 0 or 64
    int n_base = (wid & 3) * 32;      // 0,32,64,96
    int g = lane >> 3, lr = lane & 7;

    float c[4][4][4];
    #pragma unroll
    for (int i = 0; i < 4; i++)
        #pragma unroll
        for (int j = 0; j < 4; j++)
            #pragma unroll
            for (int q = 0; q < 4; q++) c[i][j][q] = 0.f;

    uint32_t As_base = smem_u32(As), Bs_base = smem_u32(Bs);
    uint32_t a_row_off = (uint32_t)((m_base + (g & 1) * 8 + lr) * ASTR + (g >> 1) * 8) * 2;
    uint32_t b_row_off = (uint32_t)((n_base + lr) * ASTR + (g & 1) * 8) * 2;

    // prologue: load chunk 0 into buffer 0
    cp_async16(sA0, gA0, okA0); cp_async16(sA1, gA1, okA1);
    cp_async16(sB0, gB0, okB0); cp_async16(sB1, gB1, okB1);
    CP_COMMIT();

    #pragma unroll
    for (int ck = 0; ck < NCHUNK; ck++) {
        int s = ck & 1;
        if (ck + 1 < NCHUNK) {
            int sn = (ck + 1) & 1;
            uint32_t so = sn * (uint32_t)ABYTES;
            int go = (ck + 1) * (KC * 2);
            cp_async16(sA0 + so, gA0 + go, okA0);
            cp_async16(sA1 + so, gA1 + go, okA1);
            cp_async16(sB0 + so, gB0 + go, okB0);
            cp_async16(sB1 + so, gB1 + go, okB1);
            CP_COMMIT();
            CP_WAIT(1);
        } else {
            CP_WAIT(0);
        }
        __syncthreads();

        uint32_t abase = As_base + s * (uint32_t)ABYTES + a_row_off;
        uint32_t bbase = Bs_base + s * (uint32_t)ABYTES + b_row_off;
        #pragma unroll
        for (int ks = 0; ks < KC; ks += 16) {
            uint32_t af[4][4], bf[4][2];
            #pragma unroll
            for (int mt = 0; mt < 4; mt++) {
                uint32_t addr = abase + (uint32_t)(mt * 16 * ASTR + ks) * 2;
                asm volatile("ldmatrix.sync.aligned.m8n8.x4.shared.b16 {%0,%1,%2,%3}, [%4];"
                             : "=r"(af[mt][0]), "=r"(af[mt][1]), "=r"(af[mt][2]), "=r"(af[mt][3])
                             : "r"(addr));
            }
            #pragma unroll
            for (int nt = 0; nt < 4; nt++) {
                uint32_t addr = bbase + (uint32_t)(nt * 8 * ASTR + ks) * 2;
                asm volatile("ldmatrix.sync.aligned.m8n8.x2.shared.b16 {%0,%1}, [%2];"
                             : "=r"(bf[nt][0]), "=r"(bf[nt][1])
                             : "r"(addr));
            }
            #pragma unroll
            for (int mt = 0; mt < 4; mt++)
                #pragma unroll
                for (int nt = 0; nt < 4; nt++) {
                    asm volatile(
                        "mma.sync.aligned.m16n8k16.row.col.f32.bf16.bf16.f32 "
                        "{%0,%1,%2,%3}, {%4,%5,%6,%7}, {%8,%9}, {%0,%1,%2,%3};"
                        : "+f"(c[mt][nt][0]), "+f"(c[mt][nt][1]),
                          "+f"(c[mt][nt][2]), "+f"(c[mt][nt][3])
                        : "r"(af[mt][0]), "r"(af[mt][1]), "r"(af[mt][2]), "r"(af[mt][3]),
                          "r"(bf[nt][0]), "r"(bf[nt][1]));
                }
        }
        __syncthreads();   // WAR guard: buffer s is rewritten at ck+2
    }

    // fused epilogue
    int qr = lane >> 2, qc = (lane & 3) * 2;
    float lsum = 0.f;
    #pragma unroll
    for (int mt = 0; mt < 4; mt++) {
        float4 r0 = s_row[m_base + mt * 16 + qr];
        float4 r1 = s_row[m_base + mt * 16 + qr + 8];
        #pragma unroll
        for (int nt = 0; nt < 4; nt++) {
            float4 c0 = s_col[n_base + nt * 8 + qc];
            float4 c1 = s_col[n_base + nt * 8 + qc + 1];
            lsum += lossterm(c[mt][nt][0], r0, c0);
            lsum += lossterm(c[mt][nt][1], r0, c1);
            lsum += lossterm(c[mt][nt][2], r1, c0);
            lsum += lossterm(c[mt][nt][3], r1, c1);
        }
    }

    float v = warpsum(lsum);
    if (lane == 0) wred[wid] = v;
    __syncthreads();
    if (tid == 0) {
        float s = 0;
        #pragma unroll
        for (int u = 0; u < 8; u++) s += wred[u];
        atomicAdd(&g_acc[7], (double)s);
    }
}

// ---------------- finalize ----------------
__global__ void finalize_kernel(float* __restrict__ out) {
    double np1 = g_acc[2];
    double pl  = (np1 == 0.0) ? -g_acc[1] : -(g_acc[0] + g_acc[1]) / fmax(np1, 1.0);
    double np2 = g_acc[5];
    double wpl = (np2 == 0.0) ? -g_acc[4] : -(g_acc[3] + g_acc[4]) / fmax(np2, 1.0);
    double dl  = g_acc[7] / g_acc[6];
    out[0] = (float)(pl + wpl + 1e-4 * dl);
    out[1] = (float)pl;
    out[2] = (float)wpl;
    out[3] = (float)dl;
}

// ---------------- launch ----------------
extern "C" void kernel_launch(void* const* d_in, const int* in_sizes, int n_in,
                              void* d_out, int out_size) {
    const float* prob  = (const float*)d_in[0];
    const float* ht    = (const float*)d_in[1];
    const float* vm    = (const float*)d_in[2];
    const float* wprob = (const float*)d_in[3];
    const float* wht   = (const float*)d_in[4];
    const float* wvm   = (const float*)d_in[5];
    const float* desc  = (const float*)d_in[6];
    const float* wdesc = (const float*)d_in[7];
    const float* Hm    = (const float*)d_in[8];
    float* out = (float*)d_out;

    init_kernel<<<1, 32>>>();
    detector_kernel<<<1184, 256>>>(prob, ht, vm, wprob, wht, wvm);

    __nv_bfloat16* dnorm;  cudaGetSymbolAddress((void**)&dnorm,  g_dnorm);
    __nv_bfloat16* wdnorm; cudaGetSymbolAddress((void**)&wdnorm, g_wdnorm);
    normdesc_kernel<<<2 * BB * (NN / 32), 256>>>(desc, dnorm, wdesc, wdnorm);

    coords_kernel<<<(BB * NN + 255) / 256, 256>>>(vm, wvm, Hm);

    dim3 grid((NN + TILE - 1) / TILE, (NN + TILE - 1) / TILE, BB);
    gemm_loss_kernel<<<grid, 256>>>();

    finalize_kernel<<<1, 1>>>(out);
}